// round 7
// baseline (speedup 1.0000x reference)
#include <cuda_runtime.h>
#include <math.h>

// Problem constants (fixed by the dataset)
#define T_TYPES 4
#define U_DIM   10
#define U_PAD   12                     // padded so each (s,t) row is 48B, 16B-aligned
#define EMB     200
#define DIM_A   20
#define TUP     (T_TYPES * U_PAD)      // 48 floats per node
#define MAX_NSRC 65536
#define MAX_NDST 8192
#define PROWS   32                     // rows per project block

// Scratch (device globals: allocation-free)
__device__ float  g_src_feat[MAX_NSRC * TUP];  // [s][t*U_PAD+u], 12.6 MB
__device__ float  g_agg[MAX_NDST * TUP];       // [b][t*U_PAD+u], 1.6 MB
__device__ float4 g_comb4[MAX_NDST * 3];       // [b][12 floats] (10 + pad)

// ---------------------------------------------------------------------------
// K1: gather node_type_embeddings rows into compact padded buffer
//     (also zeroes g_agg: disjoint buffer, rides along for free)
// ---------------------------------------------------------------------------
__global__ void gather_kernel(const int* __restrict__ input_nodes,
                              const float* __restrict__ nte_table,
                              int n_src, int n_zero4) {
    int i = blockIdx.x * blockDim.x + threadIdx.x;
    if (i < n_zero4)
        reinterpret_cast<float4*>(g_agg)[i] = make_float4(0.f, 0.f, 0.f, 0.f);
    int total = n_src * T_TYPES;
    if (i >= total) return;
    int s = i >> 2;
    int t = i & 3;
    int node = __ldg(&input_nodes[s]);
    const float2* src = reinterpret_cast<const float2*>(
        nte_table + (size_t)node * (T_TYPES * U_DIM) + t * U_DIM);
    float2* dst = reinterpret_cast<float2*>(
        g_src_feat + (size_t)s * TUP + t * U_PAD);
#pragma unroll
    for (int q = 0; q < 5; q++) dst[q] = __ldg(&src[q]);
    dst[5] = make_float2(0.0f, 0.0f);   // padding
}

// ---------------------------------------------------------------------------
// K2: per-edge scatter-add using vectorized global reductions (sm_90+)
// ---------------------------------------------------------------------------
__device__ __forceinline__ void red_v4(float* p, float4 v) {
    asm volatile("red.global.add.v4.f32 [%0], {%1, %2, %3, %4};"
                 :: "l"(p), "f"(v.x), "f"(v.y), "f"(v.z), "f"(v.w)
                 : "memory");
}
__device__ __forceinline__ void red_v2(float* p, float2 v) {
    asm volatile("red.global.add.v2.f32 [%0], {%1, %2};"
                 :: "l"(p), "f"(v.x), "f"(v.y)
                 : "memory");
}

__global__ void edge_kernel(const int* __restrict__ edge_src,
                            const int* __restrict__ edge_dst,
                            int E) {
    int idx = blockIdx.x * blockDim.x + threadIdx.x;
    int total = T_TYPES * E;
    if (idx >= total) return;
    int t = idx / E;
    int e = idx - t * E;
    int s = __ldg(&edge_src[(size_t)t * E + e]);
    int d = __ldg(&edge_dst[(size_t)t * E + e]);
    const float* src = g_src_feat + (size_t)s * TUP + t * U_PAD;   // 16B-aligned
    float*       dst = g_agg      + (size_t)d * TUP + t * U_PAD;   // 16B-aligned
    float4 a = __ldg(reinterpret_cast<const float4*>(src));
    float4 b = __ldg(reinterpret_cast<const float4*>(src + 4));
    float2 c = __ldg(reinterpret_cast<const float2*>(src + 8));
    red_v4(dst, a);
    red_v4(dst + 4, b);
    red_v2(dst + 8, c);
}

// ---------------------------------------------------------------------------
// K3a: attention + combine.  FOUR lanes per dst node (lane&3 == t).
// ---------------------------------------------------------------------------
__global__ void __launch_bounds__(256)
combine_kernel(const float* __restrict__ s1,    // [T,U,A]
               const float* __restrict__ s2,    // [T,A,1]
               int n_dst)
{
    __shared__ float s1_s[T_TYPES * U_DIM * DIM_A];   // 800 floats
    __shared__ float s2_s[T_TYPES * DIM_A];           // 80 floats

    int tid = threadIdx.x;
    for (int i = tid; i < T_TYPES * U_DIM * DIM_A; i += 256) s1_s[i] = __ldg(&s1[i]);
    if (tid < T_TYPES * DIM_A) s2_s[tid] = __ldg(&s2[tid]);
    __syncthreads();

    int gidx = blockIdx.x * blockDim.x + tid;
    int j = gidx >> 2;          // node
    int t = gidx & 3;           // edge type (lane&3 == t since blockDim%4==0)
    if (j >= n_dst) return;

    // load this lane's nte[t] row: 3 x float4 (48B aligned)
    float nte[12];
    {
        const float4* p = reinterpret_cast<const float4*>(
            g_agg + (size_t)j * TUP + t * U_PAD);
#pragma unroll
        for (int q = 0; q < 3; q++) {
            float4 v = p[q];
            nte[4 * q] = v.x; nte[4 * q + 1] = v.y;
            nte[4 * q + 2] = v.z; nte[4 * q + 3] = v.w;
        }
    }

    float score = 0.0f;
#pragma unroll
    for (int a = 0; a < DIM_A; a++) {
        float h = 0.0f;
#pragma unroll
        for (int u = 0; u < U_DIM; u++)
            h += nte[u] * s1_s[(t * U_DIM + u) * DIM_A + a];
        score += tanhf(h) * s2_s[t * DIM_A + a];
    }

    // softmax across the 4 lanes of this node
    float m = score;
    m = fmaxf(m, __shfl_xor_sync(0xffffffffu, m, 1));
    m = fmaxf(m, __shfl_xor_sync(0xffffffffu, m, 2));
    float ex = expf(score - m);
    float sum = ex;
    sum += __shfl_xor_sync(0xffffffffu, sum, 1);
    sum += __shfl_xor_sync(0xffffffffu, sum, 2);
    float att = ex / sum;

    // comb[u] = sum_t att[t] * nte[t][u]  (reduce across the 4 lanes)
    float comb[U_DIM];
#pragma unroll
    for (int u = 0; u < U_DIM; u++) {
        float v = att * nte[u];
        v += __shfl_xor_sync(0xffffffffu, v, 1);
        v += __shfl_xor_sync(0xffffffffu, v, 2);
        comb[u] = v;
    }
    if (t == 0) {
        g_comb4[j * 3 + 0] = make_float4(comb[0], comb[1], comb[2], comb[3]);
        g_comb4[j * 3 + 1] = make_float4(comb[4], comb[5], comb[6], comb[7]);
        g_comb4[j * 3 + 2] = make_float4(comb[8], comb[9], 0.0f, 0.0f);
    }
}

// ---------------------------------------------------------------------------
// K3b: projection + normalize.  Block = 256 thr, fixed t, PROWS=32 rows.
//      Batched smem staging of base+comb (huge MLP), then warp-per-row
//      compute with W[t] in 80 float regs; lane<25 owns e={4l..4l+3,
//      100+4l..100+4l+3}; all hot loads/stores 128-bit.
// ---------------------------------------------------------------------------
__global__ void __launch_bounds__(256)
project_kernel(const int*   __restrict__ output_nodes,
               const float* __restrict__ node_emb,
               const float* __restrict__ W,      // [T,U,EMB]
               float* __restrict__ out,          // [B,T,EMB]
               int n_dst)
{
    __shared__ float base_s[PROWS][EMB];    // 25.6 KB
    __shared__ float comb_s[PROWS][12];     // 1.5 KB

    int t    = blockIdx.y;
    int tid  = threadIdx.x;
    int lane = tid & 31;
    int w    = tid >> 5;                    // 8 warps
    int b0   = blockIdx.x * PROWS;
    bool act = (lane < 25);

    // --- stage W into registers (per warp, L1-hot after first warp) ---
    float4 Wa[U_DIM], Wb[U_DIM];
#pragma unroll
    for (int u = 0; u < U_DIM; u++) {
        const float* wp = W + (size_t)(t * U_DIM + u) * EMB + 4 * (act ? lane : 0);
        float4 a = __ldg(reinterpret_cast<const float4*>(wp));
        float4 b = __ldg(reinterpret_cast<const float4*>(wp + 100));
        Wa[u] = act ? a : make_float4(0.f, 0.f, 0.f, 0.f);
        Wb[u] = act ? b : make_float4(0.f, 0.f, 0.f, 0.f);
    }

    // --- stage base rows: 32 rows x 50 float4 = 1600 loads across 256 thr ---
    for (int i = tid; i < PROWS * 50; i += 256) {
        int r = i / 50, q = i - r * 50;
        int b = b0 + r;
        if (b < n_dst) {
            int node = __ldg(&output_nodes[b]);      // L1-hot broadcast
            reinterpret_cast<float4*>(base_s[r])[q] =
                __ldg(reinterpret_cast<const float4*>(node_emb + (size_t)node * EMB) + q);
        }
    }
    // --- stage comb rows: 32 x 3 float4 ---
    for (int i = tid; i < PROWS * 3; i += 256) {
        int r = i / 3, q = i - r * 3;
        if (b0 + r < n_dst)
            reinterpret_cast<float4*>(comb_s[r])[q] = g_comb4[(b0 + r) * 3 + q];
    }
    __syncthreads();

    // --- compute: warp w handles rows w*4 .. w*4+3 ---
#pragma unroll
    for (int rr = 0; rr < PROWS / 8; rr++) {
        int r = w * (PROWS / 8) + rr;
        int b = b0 + r;
        if (b >= n_dst) continue;

        float c[U_DIM];
#pragma unroll
        for (int u = 0; u < U_DIM; u++) c[u] = comb_s[r][u];   // smem broadcast

        float4 vA = make_float4(0.f, 0.f, 0.f, 0.f);
        float4 vB = vA;
        if (act) {
            vA = reinterpret_cast<const float4*>(base_s[r])[lane];
            vB = reinterpret_cast<const float4*>(base_s[r] + 100)[lane];
        }
#pragma unroll
        for (int u = 0; u < U_DIM; u++) {
            float cu = c[u];
            vA.x += cu * Wa[u].x;  vA.y += cu * Wa[u].y;
            vA.z += cu * Wa[u].z;  vA.w += cu * Wa[u].w;
            vB.x += cu * Wb[u].x;  vB.y += cu * Wb[u].y;
            vB.z += cu * Wb[u].z;  vB.w += cu * Wb[u].w;
        }
        float ssq = vA.x * vA.x + vA.y * vA.y + vA.z * vA.z + vA.w * vA.w
                  + vB.x * vB.x + vB.y * vB.y + vB.z * vB.z + vB.w * vB.w;
#pragma unroll
        for (int off = 16; off > 0; off >>= 1)
            ssq += __shfl_xor_sync(0xffffffffu, ssq, off);
        float inv = rsqrtf(fmaxf(ssq, 1e-24f));

        if (act) {
            float* o = out + ((size_t)b * T_TYPES + t) * EMB;
            vA.x *= inv; vA.y *= inv; vA.z *= inv; vA.w *= inv;
            vB.x *= inv; vB.y *= inv; vB.z *= inv; vB.w *= inv;
            reinterpret_cast<float4*>(o)[lane] = vA;
            reinterpret_cast<float4*>(o + 100)[lane] = vB;
        }
    }
}

// ---------------------------------------------------------------------------
// Launch
// ---------------------------------------------------------------------------
extern "C" void kernel_launch(void* const* d_in, const int* in_sizes, int n_in,
                              void* d_out, int out_size) {
    const int*   input_nodes  = (const int*)  d_in[0];
    const int*   output_nodes = (const int*)  d_in[1];
    const int*   edge_src     = (const int*)  d_in[2];
    const int*   edge_dst     = (const int*)  d_in[3];
    const float* node_emb     = (const float*)d_in[4];
    const float* nte_table    = (const float*)d_in[5];
    const float* W            = (const float*)d_in[6];
    const float* s1           = (const float*)d_in[7];
    const float* s2           = (const float*)d_in[8];
    float* out = (float*)d_out;

    int n_src = in_sizes[0];
    int n_dst = in_sizes[1];
    int E     = in_sizes[2] / T_TYPES;

    // K1: gather (one thread per (s,t)) + zero agg
    {
        int n_zero4 = (n_dst * TUP) / 4;
        int n = n_src * T_TYPES;
        int nthreads = n > n_zero4 ? n : n_zero4;
        gather_kernel<<<(nthreads + 255) / 256, 256>>>(input_nodes, nte_table,
                                                       n_src, n_zero4);
    }
    // K2: scatter-add over edges (vector reds)
    {
        int n = T_TYPES * E;
        edge_kernel<<<(n + 255) / 256, 256>>>(edge_src, edge_dst, E);
    }
    // K3a: attention + combine (4 lanes per node)
    {
        int n = n_dst * T_TYPES;
        combine_kernel<<<(n + 255) / 256, 256>>>(s1, s2, n_dst);
    }
    // K3b: projection + normalize (staged smem, warp-per-row, float4 lanes)
    {
        dim3 grid((n_dst + PROWS - 1) / PROWS, T_TYPES);
        project_kernel<<<grid, 256>>>(output_nodes, node_emb, W, out, n_dst);
    }
}

// round 8
// speedup vs baseline: 1.1167x; 1.1167x over previous
#include <cuda_runtime.h>
#include <math.h>

// Problem constants (fixed by the dataset)
#define T_TYPES 4
#define U_DIM   10
#define U_PAD   12                     // padded so each (s,t) row is 48B, 16B-aligned
#define EMB     200
#define DIM_A   20
#define TUP     (T_TYPES * U_PAD)      // 48 floats per node
#define MAX_NSRC 65536
#define MAX_NDST 8192
#define NSLICE  7                      // ceil(EMB/32)
#define ROWS_PW 8                      // rows per warp in project

// Scratch (device globals: allocation-free)
__device__ float g_src_feat[MAX_NSRC * TUP];   // [s][t*U_PAD+u], 12.6 MB
__device__ float g_agg[MAX_NDST * TUP];        // [b][t*U_PAD+u], 1.6 MB
__device__ float g_comb[MAX_NDST * U_DIM];     // [b][u]
__device__ float g_base[MAX_NDST * EMB];       // staged base rows, 6.5 MB (L2-resident)

// ---------------------------------------------------------------------------
// K1: fused housekeeping gathers
//   task A: zero g_agg (n_dst*TUP/4 float4 stores)
//   task B: gather node_type_embeddings -> g_src_feat (n_src*4 threads)
//   task C: stage node_emb[output_nodes[b]] -> g_base (n_dst*50 float4 copies)
// ---------------------------------------------------------------------------
__global__ void gather_kernel(const int* __restrict__ input_nodes,
                              const int* __restrict__ output_nodes,
                              const float* __restrict__ nte_table,
                              const float* __restrict__ node_emb,
                              int n_src, int n_dst, int n_zero4) {
    int i = blockIdx.x * blockDim.x + threadIdx.x;

    // task A: zero agg
    if (i < n_zero4)
        reinterpret_cast<float4*>(g_agg)[i] = make_float4(0.f, 0.f, 0.f, 0.f);

    // task C: stage base rows (dense destination, random source, huge MLP)
    int n_stage = n_dst * (EMB / 4);           // 50 float4 per row
    if (i < n_stage) {
        int b = i / (EMB / 4);
        int q = i - b * (EMB / 4);
        int node = __ldg(&output_nodes[b]);
        reinterpret_cast<float4*>(g_base + (size_t)b * EMB)[q] =
            __ldg(reinterpret_cast<const float4*>(node_emb + (size_t)node * EMB) + q);
    }

    // task B: per-(s,t) gather of type embeddings
    int total = n_src * T_TYPES;
    if (i >= total) return;
    int s = i >> 2;
    int t = i & 3;
    int node = __ldg(&input_nodes[s]);
    const float2* src = reinterpret_cast<const float2*>(
        nte_table + (size_t)node * (T_TYPES * U_DIM) + t * U_DIM);
    float2* dst = reinterpret_cast<float2*>(
        g_src_feat + (size_t)s * TUP + t * U_PAD);
#pragma unroll
    for (int q = 0; q < 5; q++) dst[q] = __ldg(&src[q]);
    dst[5] = make_float2(0.0f, 0.0f);   // padding
}

// ---------------------------------------------------------------------------
// K2: per-edge scatter-add using vectorized global reductions (sm_90+)
// ---------------------------------------------------------------------------
__device__ __forceinline__ void red_v4(float* p, float4 v) {
    asm volatile("red.global.add.v4.f32 [%0], {%1, %2, %3, %4};"
                 :: "l"(p), "f"(v.x), "f"(v.y), "f"(v.z), "f"(v.w)
                 : "memory");
}
__device__ __forceinline__ void red_v2(float* p, float2 v) {
    asm volatile("red.global.add.v2.f32 [%0], {%1, %2};"
                 :: "l"(p), "f"(v.x), "f"(v.y)
                 : "memory");
}

__global__ void edge_kernel(const int* __restrict__ edge_src,
                            const int* __restrict__ edge_dst,
                            int E) {
    int idx = blockIdx.x * blockDim.x + threadIdx.x;
    int total = T_TYPES * E;
    if (idx >= total) return;
    int t = idx / E;
    int e = idx - t * E;
    int s = __ldg(&edge_src[(size_t)t * E + e]);
    int d = __ldg(&edge_dst[(size_t)t * E + e]);
    const float* src = g_src_feat + (size_t)s * TUP + t * U_PAD;   // 16B-aligned
    float*       dst = g_agg      + (size_t)d * TUP + t * U_PAD;   // 16B-aligned
    float4 a = __ldg(reinterpret_cast<const float4*>(src));
    float4 b = __ldg(reinterpret_cast<const float4*>(src + 4));
    float2 c = __ldg(reinterpret_cast<const float2*>(src + 8));
    red_v4(dst, a);
    red_v4(dst + 4, b);
    red_v2(dst + 8, c);
}

// ---------------------------------------------------------------------------
// K3a: attention + combine.  FOUR lanes per dst node (lane&3 == t).
// ---------------------------------------------------------------------------
__global__ void __launch_bounds__(256)
combine_kernel(const float* __restrict__ s1,    // [T,U,A]
               const float* __restrict__ s2,    // [T,A,1]
               int n_dst)
{
    __shared__ float s1_s[T_TYPES * U_DIM * DIM_A];   // 800 floats
    __shared__ float s2_s[T_TYPES * DIM_A];           // 80 floats

    int tid = threadIdx.x;
    for (int i = tid; i < T_TYPES * U_DIM * DIM_A; i += 256) s1_s[i] = __ldg(&s1[i]);
    if (tid < T_TYPES * DIM_A) s2_s[tid] = __ldg(&s2[tid]);
    __syncthreads();

    int gidx = blockIdx.x * blockDim.x + tid;
    int j = gidx >> 2;          // node
    int t = gidx & 3;           // edge type (lane&3 == t since blockDim%4==0)
    if (j >= n_dst) return;

    // load this lane's nte[t] row: 3 x float4 (48B aligned)
    float nte[12];
    {
        const float4* p = reinterpret_cast<const float4*>(
            g_agg + (size_t)j * TUP + t * U_PAD);
#pragma unroll
        for (int q = 0; q < 3; q++) {
            float4 v = p[q];
            nte[4 * q] = v.x; nte[4 * q + 1] = v.y;
            nte[4 * q + 2] = v.z; nte[4 * q + 3] = v.w;
        }
    }

    float score = 0.0f;
#pragma unroll
    for (int a = 0; a < DIM_A; a++) {
        float h = 0.0f;
#pragma unroll
        for (int u = 0; u < U_DIM; u++)
            h += nte[u] * s1_s[(t * U_DIM + u) * DIM_A + a];
        score += tanhf(h) * s2_s[t * DIM_A + a];
    }

    // softmax across the 4 lanes of this node
    float m = score;
    m = fmaxf(m, __shfl_xor_sync(0xffffffffu, m, 1));
    m = fmaxf(m, __shfl_xor_sync(0xffffffffu, m, 2));
    float ex = expf(score - m);
    float sum = ex;
    sum += __shfl_xor_sync(0xffffffffu, sum, 1);
    sum += __shfl_xor_sync(0xffffffffu, sum, 2);
    float att = ex / sum;

    // comb[u] = sum_t att[t] * nte[t][u]  (reduce across the 4 lanes)
    float comb[U_DIM];
#pragma unroll
    for (int u = 0; u < U_DIM; u++) {
        float v = att * nte[u];
        v += __shfl_xor_sync(0xffffffffu, v, 1);
        v += __shfl_xor_sync(0xffffffffu, v, 2);
        comb[u] = v;
    }
    if (t == 0) {
        float2* o = reinterpret_cast<float2*>(g_comb + (size_t)j * U_DIM);
#pragma unroll
        for (int q = 0; q < 5; q++)
            o[q] = make_float2(comb[2 * q], comb[2 * q + 1]);
    }
}

// ---------------------------------------------------------------------------
// K3b: projection + normalize.  One warp owns full rows (W[t] in 70 regs),
//      8 rows per warp, double-buffered loads of L2-resident staged base.
// ---------------------------------------------------------------------------
__global__ void __launch_bounds__(128)
project_kernel(const float* __restrict__ W,      // [T,U,EMB]
               float* __restrict__ out,          // [B,T,EMB]
               int n_dst)
{
    int t    = blockIdx.y;
    int lane = threadIdx.x & 31;
    int w    = threadIdx.x >> 5;                    // 4 warps
    int b0   = blockIdx.x * (4 * ROWS_PW) + w * ROWS_PW;

    // W registers for this t: Wr[it][u] = W[t][u][it*32+lane]
    float Wr[NSLICE][U_DIM];
#pragma unroll
    for (int it = 0; it < NSLICE; it++) {
        int e = it * 32 + lane;
#pragma unroll
        for (int u = 0; u < U_DIM; u++)
            Wr[it][u] = (e < EMB) ? __ldg(&W[(size_t)(t * U_DIM + u) * EMB + e]) : 0.0f;
    }

    float c[2][U_DIM];
    float v[2][NSLICE];

    // preload row 0 (v starts as staged base — dense, L2-hit)
    if (b0 < n_dst) {
        const float* base = g_base + (size_t)b0 * EMB;
#pragma unroll
        for (int it = 0; it < NSLICE; it++) {
            int e = it * 32 + lane;
            v[0][it] = (e < EMB) ? base[e] : 0.0f;
        }
#pragma unroll
        for (int u = 0; u < U_DIM; u++)
            c[0][u] = __ldg(&g_comb[(size_t)b0 * U_DIM + u]);
    }

#pragma unroll
    for (int r = 0; r < ROWS_PW; r++) {
        const int cur = r & 1, nxt = cur ^ 1;

        // prefetch row r+1 (issued before compute so loads overlap FFMAs)
        if (r < ROWS_PW - 1) {
            int bn = b0 + r + 1;
            if (bn < n_dst) {
                const float* base = g_base + (size_t)bn * EMB;
#pragma unroll
                for (int it = 0; it < NSLICE; it++) {
                    int e = it * 32 + lane;
                    v[nxt][it] = (e < EMB) ? base[e] : 0.0f;
                }
#pragma unroll
                for (int u = 0; u < U_DIM; u++)
                    c[nxt][u] = __ldg(&g_comb[(size_t)bn * U_DIM + u]);
            }
        }

        int b = b0 + r;
        if (b < n_dst) {
            float ssq = 0.0f;
#pragma unroll
            for (int it = 0; it < NSLICE; it++) {
                float val = v[cur][it];
#pragma unroll
                for (int u = 0; u < U_DIM; u++)
                    val += c[cur][u] * Wr[it][u];
                v[cur][it] = val;
                ssq += val * val;
            }
#pragma unroll
            for (int off = 16; off > 0; off >>= 1)
                ssq += __shfl_xor_sync(0xffffffffu, ssq, off);
            float inv = rsqrtf(fmaxf(ssq, 1e-24f));

            float* o = out + ((size_t)b * T_TYPES + t) * EMB;
#pragma unroll
            for (int it = 0; it < NSLICE; it++) {
                int e = it * 32 + lane;
                if (e < EMB) o[e] = v[cur][it] * inv;
            }
        }
    }
}

// ---------------------------------------------------------------------------
// Launch
// ---------------------------------------------------------------------------
extern "C" void kernel_launch(void* const* d_in, const int* in_sizes, int n_in,
                              void* d_out, int out_size) {
    const int*   input_nodes  = (const int*)  d_in[0];
    const int*   output_nodes = (const int*)  d_in[1];
    const int*   edge_src     = (const int*)  d_in[2];
    const int*   edge_dst     = (const int*)  d_in[3];
    const float* node_emb     = (const float*)d_in[4];
    const float* nte_table    = (const float*)d_in[5];
    const float* W            = (const float*)d_in[6];
    const float* s1           = (const float*)d_in[7];
    const float* s2           = (const float*)d_in[8];
    float* out = (float*)d_out;

    int n_src = in_sizes[0];
    int n_dst = in_sizes[1];
    int E     = in_sizes[2] / T_TYPES;

    // K1: fused zero + gather + base staging
    {
        int n_zero4  = (n_dst * TUP) / 4;
        int n_gather = n_src * T_TYPES;
        int n_stage  = n_dst * (EMB / 4);
        int nthreads = n_gather;
        if (n_zero4  > nthreads) nthreads = n_zero4;
        if (n_stage  > nthreads) nthreads = n_stage;
        gather_kernel<<<(nthreads + 255) / 256, 256>>>(
            input_nodes, output_nodes, nte_table, node_emb,
            n_src, n_dst, n_zero4);
    }
    // K2: scatter-add over edges (vector reds)
    {
        int n = T_TYPES * E;
        edge_kernel<<<(n + 255) / 256, 256>>>(edge_src, edge_dst, E);
    }
    // K3a: attention + combine (4 lanes per node)
    {
        int n = n_dst * T_TYPES;
        combine_kernel<<<(n + 255) / 256, 256>>>(s1, s2, n_dst);
    }
    // K3b: projection + normalize (warp-per-row, pipelined, staged base)
    {
        int rows_per_block = 4 * ROWS_PW;   // 32
        dim3 grid((n_dst + rows_per_block - 1) / rows_per_block, T_TYPES);
        project_kernel<<<grid, 128>>>(W, out, n_dst);
    }
}